// round 1
// baseline (speedup 1.0000x reference)
#include <cuda_runtime.h>
#include <cuda_bf16.h>

// Problem constants (fixed by the dataset shapes)
#define BB   16
#define KK   64
#define HH   160
#define WW   160
#define HWC  (HH * WW)          // 25600, multiple of 32 -> warps never span a batch
#define NTHR 256
#define BLOCKS_PER_B (HWC / NTHR)   // 100
#define EPS_F 1e-5f

__device__ __forceinline__ float ex2_approx(float x) {
    float r;
    asm("ex2.approx.ftz.f32 %0, %1;" : "=f"(r) : "f"(x));
    return r;
}

__global__ __launch_bounds__(NTHR)
void recon_conf_map_kernel(const float* __restrict__ kp,    // [B,K,2] (x,y)
                           const float* __restrict__ psx,   // scalar
                           const float* __restrict__ psy,   // scalar
                           const float* __restrict__ prho,  // scalar
                           float* __restrict__ out)         // [B,K,H,W]
{
    __shared__ float skx[KK];
    __shared__ float sky[KK];

    const int b  = blockIdx.x / BLOCKS_PER_B;
    const int hw = (blockIdx.x % BLOCKS_PER_B) * NTHR + threadIdx.x;

    // Load this batch's 64 keypoints into shared (float2 = (x, y))
    if (threadIdx.x < KK) {
        float2 p = reinterpret_cast<const float2*>(kp)[b * KK + threadIdx.x];
        skx[threadIdx.x] = p.x;
        sky[threadIdx.x] = p.y;
    }
    __syncthreads();

    // Scalars (broadcast LDG, L1-cached)
    const float sx  = psx[0];
    const float sy  = psy[0];
    const float rho = prho[0];

    const float omr2 = 1.0f - rho * rho;
    const float num1 = -0.5f / omr2;
    const float den  = 1.0f / (6.2831853071795864f * sx * sy * sqrtf(omr2));
    const float L2E  = 1.4426950408889634f;   // log2(e), folded into coeffs

    // exponent (base-2) = A*dy^2 + Bc*dx^2 + Cc*dy*dx
    const float A  = num1 * L2E / (sy * sy);
    const float Bc = num1 * L2E / (sx * sx);
    const float Cc = num1 * L2E * (-2.0f * rho) / (sx * sy);

    const float fy = (float)(hw / WW);
    const float fx = (float)(hw % WW);

    float vals[KK];
    float sum = 0.0f;

#pragma unroll
    for (int k = 0; k < KK; ++k) {
        const float dy = fy - sky[k];
        const float dx = fx - skx[k];
        // e = dy*(A*dy + Cc*dx) + Bc*dx*dx   (3 FMA + 1 MUL)
        const float e = fmaf(dy, fmaf(A, dy, Cc * dx), Bc * dx * dx);
        const float v = den * ex2_approx(e);
        vals[k] = v;
        sum += v;
    }

    const float inv = __fdividef(1.0f, sum + EPS_F);

    // out[b, k, h, w]: per-k stores are 128B-coalesced per warp
    float* __restrict__ o = out + (size_t)b * KK * HWC + hw;
#pragma unroll
    for (int k = 0; k < KK; ++k) {
        o[(size_t)k * HWC] = vals[k] * inv;
    }
}

extern "C" void kernel_launch(void* const* d_in, const int* in_sizes, int n_in,
                              void* d_out, int out_size) {
    // metadata order: keypoints, std_x, std_y, correlation, DetectionMap (unused)
    const float* kp   = (const float*)d_in[0];
    const float* psx  = (const float*)d_in[1];
    const float* psy  = (const float*)d_in[2];
    const float* prho = (const float*)d_in[3];
    float* out = (float*)d_out;

    const int grid = BB * BLOCKS_PER_B;   // 1600 blocks
    recon_conf_map_kernel<<<grid, NTHR>>>(kp, psx, psy, prho, out);
}